// round 11
// baseline (speedup 1.0000x reference)
#include <cuda_runtime.h>
#include <math.h>

#define NIMG  4
#define KTOT  4507
#define PITCH 4608
#define CAND_CAP 16384
typedef unsigned long long ull;

__constant__ int c_HW[5]   = {40000, 10000, 2500, 625, 169};
__constant__ int c_AOFF[5] = {0, 120000, 150000, 157500, 159375};
__constant__ int c_KL[5]   = {1000, 1000, 1000, 1000, 507};

// ------------- scratch (static device globals; zero-init, no allocs) -------------
__device__ int           g_pos_anchor[NIMG * PITCH];
__device__ float         g_pos_logit [NIMG * PITCH];
__device__ float         g_score_srt [NIMG * PITCH];
__device__ float4        g_box       [NIMG * PITCH];
__device__ unsigned char g_lvlvalid  [NIMG * PITCH];
__device__ unsigned char g_keepj     [NIMG * PITCH];
__device__ unsigned      g_hist      [NIMG * 5 * 256];   // reset by k1c each run
__device__ int           g_ccnt      [NIMG * 5];         // reset by k1c each run
__device__ ull           g_cand      [NIMG * 5 * CAND_CAP];

// ------------- helpers -------------
__device__ __forceinline__ unsigned ordf(float f) {
    unsigned u = __float_as_uint(f);
    return u ^ ((u & 0x80000000u) ? 0xFFFFFFFFu : 0x80000000u);
}
__device__ __forceinline__ float ordinv(unsigned u) {
    unsigned m = (u & 0x80000000u) ? 0x80000000u : 0xFFFFFFFFu;
    return __uint_as_float(u ^ m);
}

template <int NT, bool DESC, typename T>
__device__ void bitonic_sort(T* s, int tid, int nthr) {
    for (int k = 2; k <= NT; k <<= 1) {
        for (int j = k >> 1; j > 0; j >>= 1) {
            __syncthreads();
            for (int i = tid; i < NT; i += nthr) {
                int ixj = i ^ j;
                if (ixj > i) {
                    T a = s[i], b = s[ixj];
                    bool up = ((i & k) == 0);
                    if (DESC) up = !up;
                    bool sw = up ? (a > b) : (a < b);
                    if (sw) { s[i] = b; s[ixj] = a; }
                }
            }
        }
    }
    __syncthreads();
}

__device__ __forceinline__ float xla_sigmoid(float x) {
    float e = expf(-x);
    return __fdiv_rn(1.0f, __fadd_rn(1.0f, e));
}

// warp-parallel threshold over hist[256]: max bin b with suffix_sum(b) >= need
// (thread 0..31 participate; result via out_prefix/out_need shared slots)
__device__ __forceinline__ void find_thresh_warp(
    const unsigned* hist, unsigned prefix, int shift, int need,
    unsigned* out_prefix, int* out_need, int tid)
{
    const unsigned FULL = 0xFFFFFFFFu;
    if (tid < 32) {
        int lane = tid;
        unsigned c[8]; unsigned tot = 0;
        #pragma unroll
        for (int q = 0; q < 8; q++) { c[q] = hist[lane * 8 + q]; tot += c[q]; }
        unsigned suf = tot;
        #pragma unroll
        for (int o = 1; o < 32; o <<= 1) {
            unsigned v = __shfl_down_sync(FULL, suf, o);
            if (lane + o < 32) suf += v;
        }
        unsigned above = suf - tot;
        int bb = -1; unsigned run = above, Sb = 0;
        #pragma unroll
        for (int q = 7; q >= 0; q--) {
            run += c[q];
            if (bb < 0 && run >= (unsigned)need) { bb = lane * 8 + q; Sb = run; }
        }
        unsigned mask = __ballot_sync(FULL, bb >= 0);
        int hl = 31 - __clz(mask);
        if (lane == hl) {
            *out_prefix = prefix | ((unsigned)bb << shift);
            *out_need = need - (int)(Sb - hist[bb]);
        }
    }
}

// ------------- K1a: chip-wide top-byte histogram (grid 5x4x8) -------------
__global__ __launch_bounds__(512) void k1a_hist(
    const float* __restrict__ o0, const float* __restrict__ o1,
    const float* __restrict__ o2, const float* __restrict__ o3,
    const float* __restrict__ o4)
{
    __shared__ unsigned whist[16 * 256];
    const int lvl = blockIdx.x, n = blockIdx.y, sl = blockIdx.z, tid = threadIdx.x;
    const int wid = tid >> 5;
    const float* objs[5] = {o0, o1, o2, o3, o4};
    const int HW = c_HW[lvl];
    const float* base = objs[lvl] + (size_t)n * 3 * HW;
    const int idx = n * 5 + lvl;

    for (int t = tid; t < 16 * 256; t += 512) whist[t] = 0;
    __syncthreads();
    unsigned* wh = &whist[wid * 256];
    if (lvl < 3) {
        const float4* b4 = (const float4*)base;
        const int NV = (3 * HW) >> 2;
        const int NVs = (NV + 7) / 8;
        const int v0 = sl * NVs, v1 = min(v0 + NVs, NV);
        for (int v = v0 + tid; v < v1; v += 1024) {
            bool ib = (v + 512) < v1;
            float4 xa = b4[v];
            float4 xb = ib ? b4[v + 512] : make_float4(0.f, 0.f, 0.f, 0.f);
            atomicAdd(&wh[ordf(xa.x) >> 24], 1u);
            atomicAdd(&wh[ordf(xa.y) >> 24], 1u);
            atomicAdd(&wh[ordf(xa.z) >> 24], 1u);
            atomicAdd(&wh[ordf(xa.w) >> 24], 1u);
            if (ib) {
                atomicAdd(&wh[ordf(xb.x) >> 24], 1u);
                atomicAdd(&wh[ordf(xb.y) >> 24], 1u);
                atomicAdd(&wh[ordf(xb.z) >> 24], 1u);
                atomicAdd(&wh[ordf(xb.w) >> 24], 1u);
            }
        }
    } else {
        const int NT3 = 3 * HW;
        const int qs = (NT3 + 7) / 8;
        const int q0 = sl * qs, q1 = min(q0 + qs, NT3);
        for (int q = q0 + tid; q < q1; q += 512)
            atomicAdd(&wh[ordf(base[q]) >> 24], 1u);
    }
    __syncthreads();
    if (tid < 256) {
        unsigned s = 0;
        #pragma unroll
        for (int w = 0; w < 16; w++) s += whist[w * 256 + tid];
        if (s) atomicAdd(&g_hist[idx * 256 + tid], s);
    }
}

// ------------- K1b: chip-wide candidate collection (grid 5x4x8) -------------
__global__ __launch_bounds__(512) void k1b_collect(
    const float* __restrict__ o0, const float* __restrict__ o1,
    const float* __restrict__ o2, const float* __restrict__ o3,
    const float* __restrict__ o4)
{
    __shared__ unsigned hist[256];
    __shared__ unsigned s_prefix;
    __shared__ int s_need;
    const int lvl = blockIdx.x, n = blockIdx.y, sl = blockIdx.z, tid = threadIdx.x;
    const int lane = tid & 31;
    const float* objs[5] = {o0, o1, o2, o3, o4};
    const int HW = c_HW[lvl], k = c_KL[lvl], aoff = c_AOFF[lvl];
    const float* base = objs[lvl] + (size_t)n * 3 * HW;
    const int idx = n * 5 + lvl;
    const unsigned FULL = 0xFFFFFFFFu;

    if (tid < 256) hist[tid] = g_hist[idx * 256 + tid];
    __syncthreads();
    find_thresh_warp(hist, 0u, 24, k, &s_prefix, &s_need, tid);
    __syncthreads();
    const unsigned bstar = s_prefix >> 24;

    auto emit = [&](bool sel, unsigned u, int p) {
        unsigned m = __ballot_sync(FULL, sel);
        if (m) {
            int bse = 0;
            int ldr = __ffs(m) - 1;
            if (lane == ldr) bse = atomicAdd(&g_ccnt[idx], __popc(m));
            bse = __shfl_sync(FULL, bse, ldr);
            if (sel) {
                int s = bse + __popc(m & ((1u << lane) - 1u));
                if (s < CAND_CAP)
                    g_cand[idx * CAND_CAP + s] =
                        ((ull)u << 32) | (unsigned)~(unsigned)(aoff + p);
            }
        }
    };
    if (lvl < 3) {
        for (int a = 0; a < 3; a++) {
            const float4* pl4 = (const float4*)(base + a * HW);
            const int NV = HW >> 2;
            const int NVs = (NV + 7) / 8;
            const int v0 = sl * NVs, v1 = min(v0 + NVs, NV);
            const int span = v1 - v0;
            const int spanp = (span + 511) & ~511;
            for (int vv = tid; vv < spanp; vv += 512) {
                int v = v0 + vv;
                bool in = vv < span;
                float4 xa = in ? pl4[v] : make_float4(0.f, 0.f, 0.f, 0.f);
                float xs[4] = {xa.x, xa.y, xa.z, xa.w};
                #pragma unroll
                for (int e = 0; e < 4; e++) {
                    unsigned u = ordf(xs[e]);
                    emit(in && ((u >> 24) >= bstar), u, (v * 4 + e) * 3 + a);
                }
            }
        }
    } else {
        for (int a = 0; a < 3; a++) {
            const float* pl = base + a * HW;
            const int hs = (HW + 7) / 8;
            const int h0 = sl * hs, h1 = min(h0 + hs, HW);
            const int span = h1 - h0;
            const int spanp = (span + 511) & ~511;
            for (int hh = tid; hh < spanp; hh += 512) {
                int hw = h0 + hh;
                bool in = hh < span;
                unsigned u = in ? ordf(pl[hw]) : 0u;
                emit(in && ((u >> 24) >= bstar), u, hw * 3 + a);
            }
        }
    }
}

// ------------- K1c: per-(level,image) select + rank sort (grid 5x4) -------------
__global__ __launch_bounds__(512) void k1c_select()
{
    extern __shared__ ull cand[];                 // CAND_CAP u64 (128 KB)
    __shared__ unsigned hist[256];
    __shared__ ull      skey[1024];
    __shared__ unsigned eqbuf[1024];
    __shared__ int s_cntG, s_cntE;
    __shared__ unsigned s_prefix;
    __shared__ int s_need;

    const int lvl = blockIdx.x, n = blockIdx.y, tid = threadIdx.x;
    const int lane = tid & 31;
    const int k = c_KL[lvl];
    const int idx = n * 5 + lvl;
    const unsigned FULL = 0xFFFFFFFFu;

    if (tid < 256) hist[tid] = g_hist[idx * 256 + tid];
    __syncthreads();
    if (tid < 256) g_hist[idx * 256 + tid] = 0;   // reset for next run
    find_thresh_warp(hist, 0u, 24, k, &s_prefix, &s_need, tid);
    __syncthreads();
    unsigned prefix = s_prefix; int need = s_need;

    const int C = min(g_ccnt[idx], CAND_CAP);
    if (tid == 0) g_ccnt[idx] = 0;                // reset for next run
    for (int t = tid; t < C; t += 512) cand[t] = g_cand[idx * CAND_CAP + t];
    __syncthreads();

    // radix passes bytes 2,1,0 over candidates
    for (int shift = 16; shift >= 0; shift -= 8) {
        if (tid < 256) hist[tid] = 0;
        __syncthreads();
        unsigned hm = 0xFFFFFFFFu << (shift + 8);
        for (int t = tid; t < C; t += 512) {
            unsigned u = (unsigned)(cand[t] >> 32);
            if ((u & hm) == prefix) atomicAdd(&hist[(u >> shift) & 255], 1u);
        }
        __syncthreads();
        find_thresh_warp(hist, prefix, shift, need, &s_prefix, &s_need, tid);
        __syncthreads();
        prefix = s_prefix; need = s_need;
        __syncthreads();
    }
    const unsigned T = prefix;
    const int k_eq = need;

    if (tid == 0) { s_cntG = 0; s_cntE = 0; }
    __syncthreads();
    for (int t0 = tid; t0 < ((C + 511) & ~511); t0 += 512) {
        bool in = t0 < C;
        ull key = in ? cand[t0] : 0ULL;
        unsigned u = (unsigned)(key >> 32);
        bool isG = in && (u > T);
        bool isE = in && (u == T);
        unsigned mG = __ballot_sync(FULL, isG);
        if (mG) {
            int ldr = __ffs(mG) - 1; int bse = 0;
            if (lane == ldr) bse = atomicAdd(&s_cntG, __popc(mG));
            bse = __shfl_sync(FULL, bse, ldr);
            if (isG) skey[bse + __popc(mG & ((1u << lane) - 1u))] = key;
        }
        unsigned mE = __ballot_sync(FULL, isE);
        if (mE) {
            int ldr = __ffs(mE) - 1; int bse = 0;
            if (lane == ldr) bse = atomicAdd(&s_cntE, __popc(mE));
            bse = __shfl_sync(FULL, bse, ldr);
            if (isE) {
                int e = bse + __popc(mE & ((1u << lane) - 1u));
                if (e < 1024) eqbuf[e] = ~(unsigned)(key & 0xFFFFFFFFull);
            }
        }
    }
    __syncthreads();
    const int cntG = s_cntG, cntE = s_cntE;
    for (int t = tid; t < 1024; t += 512) if (t >= cntE) eqbuf[t] = 0xFFFFFFFFu;
    bitonic_sort<1024, false, unsigned>(eqbuf, tid, 512);   // index ascending
    for (int t = tid; t < k_eq; t += 512)
        skey[cntG + t] = ((ull)T << 32) | (unsigned)~eqbuf[t];
    for (int t = tid; t < 1024; t += 512) if (t >= k) skey[t] = 0ULL;
    bitonic_sort<1024, true, ull>(skey, tid, 512);          // (logit desc, idx asc)
    for (int r = tid; r < k; r += 512) {
        ull kk = skey[r];
        unsigned idxa = ~(unsigned)(kk & 0xFFFFFFFFull);
        g_pos_anchor[n * PITCH + lvl * 1000 + r] = (int)idxa;
        g_pos_logit [n * PITCH + lvl * 1000 + r] = ordinv((unsigned)(kk >> 32));
    }
}

// ------------- K2: merge-sort + fused decode (grid 4) -------------
__global__ __launch_bounds__(1024) void k2_sort_decode(
    const float* __restrict__ d0, const float* __restrict__ d1,
    const float* __restrict__ d2, const float* __restrict__ d3,
    const float* __restrict__ d4, const float* __restrict__ anch)
{
    extern __shared__ ull sk[];
    const int n = blockIdx.x, tid = threadIdx.x;
    for (int t = tid; t < 8192; t += 1024) {
        int pos = -1;
        if (t < 1024)      { if (t < 1000) pos = t; }
        else if (t < 2048) { int r = 2047 - t; if (r < 1000) pos = 1000 + r; }
        else if (t < 3072) { int r = t - 2048; if (r < 1000) pos = 2000 + r; }
        else if (t < 4096) { int r = 4095 - t; if (r < 1000) pos = 3000 + r; }
        else               { int r = 8191 - t; if (r < 507)  pos = 4000 + r; }
        ull key = 0ULL;
        if (pos >= 0) {
            float s = xla_sigmoid(g_pos_logit[n * PITCH + pos]);
            key = ((ull)ordf(s) << 32) | (unsigned)(65535 - pos);
        }
        sk[t] = key;
    }
    for (int j = 1024; j > 0; j >>= 1) {
        __syncthreads();
        for (int i = tid; i < 4096; i += 1024) {
            int ixj = i ^ j;
            if (ixj > i) {
                bool descd = (i < 2048);
                ull a = sk[i], b = sk[ixj];
                bool sw = descd ? (a < b) : (a > b);
                if (sw) { sk[i] = b; sk[ixj] = a; }
            }
        }
    }
    for (int j = 2048; j > 0; j >>= 1) {
        __syncthreads();
        for (int i = tid; i < 4096; i += 1024) {
            int ixj = i ^ j;
            if (ixj > i) {
                ull a = sk[i], b = sk[ixj];
                if (a < b) { sk[i] = b; sk[ixj] = a; }
            }
        }
    }
    for (int j = 4096; j > 0; j >>= 1) {
        __syncthreads();
        for (int i = tid; i < 8192; i += 1024) {
            int ixj = i ^ j;
            if (ixj > i) {
                ull a = sk[i], b = sk[ixj];
                if (a < b) { sk[i] = b; sk[ixj] = a; }
            }
        }
    }
    __syncthreads();
    // fused decode + clip + validity
    const float* dls[5] = {d0, d1, d2, d3, d4};
    for (int t = tid; t < KTOT; t += 1024) {
        ull key = sk[t];
        int pos = 65535 - (int)(key & 0xFFFFull);
        g_score_srt[n * PITCH + t] = ordinv((unsigned)(key >> 32));
        int idx = g_pos_anchor[n * PITCH + pos];
        int lvl = pos / 1000;
        int HW = c_HW[lvl];
        int p = idx - c_AOFF[lvl];
        int a = p % 3, hw = p / 3;
        const float* dl = dls[lvl] + (size_t)n * 12 * HW + (size_t)(a * 4) * HW + hw;
        float dx = dl[0], dy = dl[HW], dwv = dl[2 * HW], dhv = dl[3 * HW];
        float4 an = ((const float4*)anch)[idx];
        float wa  = __fsub_rn(an.z, an.x), ha = __fsub_rn(an.w, an.y);
        float cxa = __fadd_rn(an.x, __fmul_rn(0.5f, wa));
        float cya = __fadd_rn(an.y, __fmul_rn(0.5f, ha));
        const float CL = 4.135166556742356f;
        dwv = fminf(dwv, CL); dhv = fminf(dhv, CL);
        float cx = __fadd_rn(__fmul_rn(dx, wa), cxa);
        float cy = __fadd_rn(__fmul_rn(dy, ha), cya);
        float w = __fmul_rn(expf(dwv), wa);
        float h = __fmul_rn(expf(dhv), ha);
        float x1 = __fsub_rn(cx, __fmul_rn(0.5f, w));
        float y1 = __fsub_rn(cy, __fmul_rn(0.5f, h));
        float x2 = __fadd_rn(cx, __fmul_rn(0.5f, w));
        float y2 = __fadd_rn(cy, __fmul_rn(0.5f, h));
        x1 = fminf(fmaxf(x1, 0.f), 800.f);  y1 = fminf(fmaxf(y1, 0.f), 800.f);
        x2 = fminf(fmaxf(x2, 0.f), 800.f);  y2 = fminf(fmaxf(y2, 0.f), 800.f);
        int valid = (__fsub_rn(x2, x1) >= 1e-3f) && (__fsub_rn(y2, y1) >= 1e-3f);
        g_box[n * PITCH + t] = make_float4(x1, y1, x2, y2);
        g_lvlvalid[n * PITCH + t] = (unsigned char)((lvl << 1) | valid);
    }
}

// ------------- K4: fused list build + IoU bits (smem) + greedy scan (grid 5x4) ----
__global__ __launch_bounds__(512) void k4_nms()
{
    extern __shared__ ull sbits[];                // 1024*16 u64 = 128 KB
    __shared__ float4 sb[1024];
    __shared__ float  sa[1024];
    __shared__ int    ilist[1024];
    __shared__ unsigned char svalid[1024];
    __shared__ unsigned vmask[32];
    __shared__ int swsum[16];
    const int lvl = blockIdx.x, n = blockIdx.y, tid = threadIdx.x;
    const int wid = tid >> 5, lane = tid & 31;
    const int M = c_KL[lvl];
    const unsigned FULL = 0xFFFFFFFFu;

    // --- phase A: stable list build for this level ---
    unsigned char lvr[9];
    #pragma unroll
    for (int c = 0; c < 9; c++) {
        int j = c * 512 + tid;
        lvr[c] = (j < KTOT) ? g_lvlvalid[n * PITCH + j] : (unsigned char)0xFE;
    }
    int base = 0;
    const float of = __fmul_rn((float)lvl, 801.0f);
    #pragma unroll
    for (int c = 0; c < 9; c++) {
        int j = c * 512 + tid;
        unsigned char lv = lvr[c];
        int flag = ((lv >> 1) == lvl);
        unsigned wm = __ballot_sync(FULL, flag);
        int wpre = __popc(wm & ((1u << lane) - 1u));
        if (lane == 0) swsum[wid] = __popc(wm);
        __syncthreads();
        if (tid < 32) {
            int v = (lane < 16) ? swsum[lane] : 0;
            for (int o = 1; o < 16; o <<= 1) {
                int t2 = __shfl_up_sync(FULL, v, o);
                if (lane >= o) v += t2;
            }
            if (lane < 16) swsum[lane] = v;
        }
        __syncthreads();
        if (flag) {
            int r = base + (wid ? swsum[wid - 1] : 0) + wpre;
            ilist[r] = j;
            float4 b = g_box[n * PITCH + j];
            float bx = __fadd_rn(b.x, of), by = __fadd_rn(b.y, of);
            float bz = __fadd_rn(b.z, of), bw = __fadd_rn(b.w, of);
            sb[r] = make_float4(bx, by, bz, bw);
            sa[r] = __fmul_rn(__fsub_rn(bz, bx), __fsub_rn(bw, by));
            svalid[r] = lv & 1;
        }
        base += swsum[15];
        __syncthreads();
    }

    // --- phase B: IoU>0.7 bit matrix into smem ---
    const int W = (M + 63) >> 6;
    for (int t = tid; t < M * W; t += 512) {
        int i = t / W, w = t % W;
        int jstart = w << 6;
        int jend = min(jstart + 64, M);
        int js = max(jstart, i + 1);
        ull bits = 0;
        if (js < jend) {
            float4 bi = sb[i]; float ai = sa[i];
            for (int j = js; j < jend; j++) {
                float4 bj = sb[j];
                float ltx = fmaxf(bi.x, bj.x), lty = fmaxf(bi.y, bj.y);
                float rbx = fminf(bi.z, bj.z), rby = fminf(bi.w, bj.w);
                float wx = fmaxf(__fsub_rn(rbx, ltx), 0.f);
                float wy = fmaxf(__fsub_rn(rby, lty), 0.f);
                float inter = __fmul_rn(wx, wy);
                float uni = __fsub_rn(__fadd_rn(ai, sa[j]), inter);
                if (inter > __fmul_rn(0.7f, uni)) bits |= 1ull << (j - jstart);
            }
        }
        sbits[i * 16 + w] = bits;
    }
    // validity bitmask
    #pragma unroll
    for (int c0 = 0; c0 < 1024; c0 += 512) {
        int i = c0 + tid;
        int v = (i < M) ? (int)svalid[i] : 0;
        unsigned m = __ballot_sync(FULL, v);
        if (lane == 0) vmask[(c0 >> 5) + wid] = m;
    }
    __syncthreads();

    // --- phase C: greedy scan (one warp) ---
    if (tid < 32) {
        ull sup = 0;
        ull val = (lane < 16)
            ? ((ull)vmask[lane * 2] | ((ull)vmask[lane * 2 + 1] << 32)) : 0ULL;
        ull nxt = (lane < 16) ? sbits[lane] : 0;
        for (int i = 0; i < M; i++) {
            ull cur = nxt;
            if (i + 1 < M) nxt = (lane < 16) ? sbits[(i + 1) * 16 + lane] : 0;
            int wi = i >> 6, bi = i & 63;
            ull freew = (~sup) & val;
            ull fw = __shfl_sync(FULL, freew, wi);
            int kept = (int)((fw >> bi) & 1ull);
            if (kept) sup |= cur;
            if (lane == 0)
                g_keepj[n * PITCH + ilist[i]] = (unsigned char)kept;
        }
    }
}

// ------------- K5: stable keep-compaction -> output [fb | fs] -------------
__global__ __launch_bounds__(512) void k5_out(float* __restrict__ out)
{
    __shared__ int swsum[16];
    const int n = blockIdx.x, tid = threadIdx.x;
    const int wid = tid >> 5, lane = tid & 31;
    const unsigned FULL = 0xFFFFFFFFu;
    unsigned char kf[9];
    #pragma unroll
    for (int c = 0; c < 9; c++) {
        int j = c * 512 + tid;
        kf[c] = (j < KTOT) ? g_keepj[n * PITCH + j] : (unsigned char)0;
    }
    for (int t = tid; t < 4000; t += 512) out[n * 4000 + t] = 0.f;
    for (int t = tid; t < 1000; t += 512) out[16000 + n * 1000 + t] = 0.f;
    int base = 0;
    #pragma unroll
    for (int c = 0; c < 9; c++) {
        int j = c * 512 + tid;
        int flag = kf[c];
        unsigned wm = __ballot_sync(FULL, flag);
        int wpre = __popc(wm & ((1u << lane) - 1u));
        if (lane == 0) swsum[wid] = __popc(wm);
        __syncthreads();
        if (tid < 32) {
            int v = (lane < 16) ? swsum[lane] : 0;
            for (int o = 1; o < 16; o <<= 1) {
                int t2 = __shfl_up_sync(FULL, v, o);
                if (lane >= o) v += t2;
            }
            if (lane < 16) swsum[lane] = v;
        }
        __syncthreads();
        if (flag) {
            int r = base + (wid ? swsum[wid - 1] : 0) + wpre;
            if (r < 1000) {
                float4 b = g_box[n * PITCH + j];
                float* o = out + (size_t)(n * 1000 + r) * 4;
                o[0] = b.x; o[1] = b.y; o[2] = b.z; o[3] = b.w;
                out[16000 + n * 1000 + r] = g_score_srt[n * PITCH + j];
            }
        }
        base += swsum[15];
        __syncthreads();
    }
}

extern "C" void kernel_launch(void* const* d_in, const int* in_sizes, int n_in,
                              void* d_out, int out_size) {
    const float *obj[5], *del[5], *anch;
    if (in_sizes[1] == 1920000) {   // interleaved: obj0,delta0,obj1,delta1,...
        for (int i = 0; i < 5; i++) { obj[i] = (const float*)d_in[2*i]; del[i] = (const float*)d_in[2*i+1]; }
    } else {                        // grouped: obj0..obj4, delta0..delta4
        for (int i = 0; i < 5; i++) { obj[i] = (const float*)d_in[i]; del[i] = (const float*)d_in[5+i]; }
    }
    anch = (const float*)d_in[10];

    cudaFuncSetAttribute(k1c_select, cudaFuncAttributeMaxDynamicSharedMemorySize, CAND_CAP * 8);
    cudaFuncSetAttribute(k2_sort_decode, cudaFuncAttributeMaxDynamicSharedMemorySize, 65536);
    cudaFuncSetAttribute(k4_nms, cudaFuncAttributeMaxDynamicSharedMemorySize, 131072);

    k1a_hist      <<<dim3(5, 4, 8), 512>>>(obj[0], obj[1], obj[2], obj[3], obj[4]);
    k1b_collect   <<<dim3(5, 4, 8), 512>>>(obj[0], obj[1], obj[2], obj[3], obj[4]);
    k1c_select    <<<dim3(5, 4), 512, CAND_CAP * 8>>>();
    k2_sort_decode<<<4, 1024, 65536>>>(del[0], del[1], del[2], del[3], del[4], anch);
    k4_nms        <<<dim3(5, 4), 512, 131072>>>();
    k5_out        <<<4, 512>>>((float*)d_out);
    (void)n_in; (void)out_size;
}